// round 9
// baseline (speedup 1.0000x reference)
#include <cuda_runtime.h>
#include <cuda_fp16.h>
#include <math.h>
#include <stdint.h>

#define NRES 8192
#define NK   48
#define NH   128

__device__ float g_Pi[NRES * NH];
__device__ float g_Pj[NRES * NH];
__device__ float g_Ps[NRES * NH];
__device__ float g_S [NRES * NH];

__device__ __forceinline__ float gelu_exact(float x) {
    return 0.5f * x * (1.0f + erff(x * 0.7071067811865475f));
}
__device__ __forceinline__ uint32_t smem_u32(const void* p) {
    uint32_t a;
    asm("{ .reg .u64 t; cvta.to.shared.u64 t, %1; cvt.u32.u64 %0, t; }" : "=r"(a) : "l"(p));
    return a;
}
__device__ __forceinline__ uint32_t pack_h2(float a, float b) {
    __half2 h = __floats2half2_rn(a, b);
    return *reinterpret_cast<uint32_t*>(&h);
}
__device__ __forceinline__ void ldm_x4(uint32_t& r0, uint32_t& r1, uint32_t& r2, uint32_t& r3, uint32_t a) {
    asm volatile("ldmatrix.sync.aligned.m8n8.x4.shared.b16 {%0,%1,%2,%3}, [%4];"
                 : "=r"(r0), "=r"(r1), "=r"(r2), "=r"(r3) : "r"(a));
}
__device__ __forceinline__ void ldm_x2(uint32_t& r0, uint32_t& r1, uint32_t a) {
    asm volatile("ldmatrix.sync.aligned.m8n8.x2.shared.b16 {%0,%1}, [%2];"
                 : "=r"(r0), "=r"(r1) : "r"(a));
}
__device__ __forceinline__ void mma_f16(float* c, uint32_t a0, uint32_t a1, uint32_t a2, uint32_t a3,
                                        uint32_t b0, uint32_t b1) {
    asm volatile("mma.sync.aligned.m16n8k16.row.col.f32.f16.f16.f32 "
                 "{%0,%1,%2,%3}, {%4,%5,%6,%7}, {%8,%9}, {%0,%1,%2,%3};"
                 : "+f"(c[0]), "+f"(c[1]), "+f"(c[2]), "+f"(c[3])
                 : "r"(a0), "r"(a1), "r"(a2), "r"(a3), "r"(b0), "r"(b1));
}

// ---------------------------------------------------------------------------
// Kernel 1: Pi/Pj/Ps projections (fp32, conflict-free columns) — proven
// ---------------------------------------------------------------------------
__global__ __launch_bounds__(256) void k1_pre(const float* __restrict__ node_h,
                                              const float* __restrict__ seq_emb,
                                              const float* __restrict__ mW1) {
    extern __shared__ float sm1[];
    float* Wsh = sm1;
    float* Ash = sm1 + 16384;
    const int tid   = threadIdx.x;
    const int which = blockIdx.y;
    const float* A    = (which == 2) ? seq_emb : node_h;
    const float* Wsrc = mW1 + (size_t)(which == 0 ? 0 : (which == 1 ? 128 : 384)) * NH;
    float* out = (which == 0) ? g_Pi : (which == 1 ? g_Pj : g_Ps);

    for (int i = tid; i < 4096; i += 256) ((float4*)Wsh)[i] = ((const float4*)Wsrc)[i];
    const int m0 = blockIdx.x * 64;
    for (int i = tid; i < 2048; i += 256) {
        int r = i >> 5, c4 = i & 31;
        *(float4*)&Ash[r * 132 + c4 * 4] = ((const float4*)(A + (size_t)(m0 + r) * NH))[c4];
    }
    __syncthreads();
    const int tc = tid & 15, tr = tid >> 4;
    float acc[4][8];
#pragma unroll
    for (int i = 0; i < 4; i++)
#pragma unroll
        for (int j = 0; j < 8; j++) acc[i][j] = 0.f;
#pragma unroll 4
    for (int kk = 0; kk < 128; kk++) {
        float4 b0 = *(const float4*)&Wsh[kk * 128 + tc * 4];
        float4 b1 = *(const float4*)&Wsh[kk * 128 + 64 + tc * 4];
#pragma unroll
        for (int i = 0; i < 4; i++) {
            float a = Ash[(tr * 4 + i) * 132 + kk];
            acc[i][0] = fmaf(a, b0.x, acc[i][0]); acc[i][1] = fmaf(a, b0.y, acc[i][1]);
            acc[i][2] = fmaf(a, b0.z, acc[i][2]); acc[i][3] = fmaf(a, b0.w, acc[i][3]);
            acc[i][4] = fmaf(a, b1.x, acc[i][4]); acc[i][5] = fmaf(a, b1.y, acc[i][5]);
            acc[i][6] = fmaf(a, b1.z, acc[i][6]); acc[i][7] = fmaf(a, b1.w, acc[i][7]);
        }
    }
#pragma unroll
    for (int i = 0; i < 4; i++) {
        size_t r = (size_t)(m0 + tr * 4 + i) * NH;
        *(float4*)&out[r + tc * 4]      = make_float4(acc[i][0], acc[i][1], acc[i][2], acc[i][3]);
        *(float4*)&out[r + 64 + tc * 4] = make_float4(acc[i][4], acc[i][5], acc[i][6], acc[i][7]);
    }
}

// ---------------------------------------------------------------------------
// Kernel 2: per-edge MLP, single-pass fp16 HMMA (A fp16, W fp16).
// cp.async pipeline + warp-shuffle segmented reduction (both proven).
// ---------------------------------------------------------------------------
#define LDB 272u
#define S_W1  0u
#define S_W2  34816u
#define S_A   69632u
#define S_STG 104448u
#define S_SSUM 153600u
#define S_IDX 157696u
#define S_AM  158720u
#define S_MB  159744u
#define S_K2TOT 160768u

__device__ __forceinline__ void do_prefetch(uint32_t sb, const float* edge_h,
                                            const int* edge_idx, const float* ar_mask,
                                            int row0, int pp, int tid) {
    const char* src = (const char*)(edge_h + (size_t)row0 * NH);
#pragma unroll
    for (int k = 0; k < 6; k++) {
        uint32_t off = (uint32_t)(tid + k * 512) * 16u;
        asm volatile("cp.async.cg.shared.global [%0], [%1], 16;"
                     :: "r"(sb + S_STG + off), "l"(src + off));
    }
    if (tid < 128)
        asm volatile("cp.async.ca.shared.global [%0], [%1], 4;"
                     :: "r"(sb + S_IDX + (uint32_t)pp * 512u + (uint32_t)tid * 4u),
                        "l"(edge_idx + row0 + tid));
    else if (tid < 256)
        asm volatile("cp.async.ca.shared.global [%0], [%1], 4;"
                     :: "r"(sb + S_AM + (uint32_t)pp * 512u + (uint32_t)(tid - 128) * 4u),
                        "l"(ar_mask + row0 + (tid - 128)));
    asm volatile("cp.async.commit_group;" ::: "memory");
}

__global__ __launch_bounds__(512) void k2_msg(const float* __restrict__ edge_h,
                                              const int*   __restrict__ edge_idx,
                                              const float* __restrict__ ar_mask,
                                              const float* __restrict__ mW1,
                                              const float* __restrict__ mb1,
                                              const float* __restrict__ mW2,
                                              const float* __restrict__ mb2,
                                              int ngroups) {
    extern __shared__ char sm[];
    const int tid  = threadIdx.x;
    const int w    = tid >> 5, lane = tid & 31;
    const int gid  = lane >> 2, t4 = lane & 3;
    const int wm   = w >> 2, wn = w & 3;
    const int m_base = wm * 32, n_base = wn * 32;
    const uint32_t sb = smem_u32(sm);

    float* SSUM = (float*)(sm + S_SSUM);
    float* MB   = (float*)(sm + S_MB);
    float* STG  = (float*)(sm + S_STG);

    if (tid < 128) MB[tid] = mb1[tid];
    else if (tid < 256) MB[tid] = mb2[tid - 128];

    // stage W1c^T / W2^T as fp16 (coalesced reads)
    for (int idx = tid; idx < 16384; idx += 512) {
        const int n = idx & 127, k = idx >> 7;
        float w1 = mW1[(size_t)(256 + k) * NH + n];
        float w2 = mW2[(size_t)k * NH + n];
        const uint32_t o = (uint32_t)n * LDB + (uint32_t)k * 2u;
        *(__half*)(sm + S_W1 + o) = __float2half_rn(w1);
        *(__half*)(sm + S_W2 + o) = __float2half_rn(w2);
    }

    const uint32_t aBase = sb + S_A + (uint32_t)(m_base + (lane & 15)) * LDB
                         + (uint32_t)((lane >> 4) * 16);
    const uint32_t b_off = (uint32_t)(lane & 7) * LDB + (uint32_t)(((lane >> 3) & 1) * 16);
    uint32_t bOf[4];
#pragma unroll
    for (int j = 0; j < 4; j++)
        bOf[j] = (uint32_t)(n_base + j * 8) * LDB + b_off;

    int pp = 0;
    if ((int)blockIdx.x < ngroups)
        do_prefetch(sb, edge_h, edge_idx, ar_mask, blockIdx.x * 384, 0, tid);

    for (int g = blockIdx.x; g < ngroups; g += gridDim.x) {
        for (int t = 0; t < 3; t++) {
            const int row0 = g * 384 + t * 128;
            asm volatile("cp.async.wait_group 0;" ::: "memory");
            __syncthreads();
            if (t == 0)
                for (int i = tid; i < 1024; i += 512) SSUM[i] = 0.f;

            // staged rows 0-95 -> A fp16
#pragma unroll
            for (int k2i = 0; k2i < 6; k2i++) {
                const int i = tid + k2i * 512;
                const int r = i >> 5, c4 = i & 31;
                float4 e = *(const float4*)((const char*)STG + (size_t)i * 16);
                const uint32_t o = (uint32_t)r * LDB + (uint32_t)c4 * 8u;
                *(uint2*)(sm + S_A + o) = make_uint2(pack_h2(e.x, e.y), pack_h2(e.z, e.w));
            }
            // direct rows 96-127
#pragma unroll
            for (int k2i = 0; k2i < 2; k2i++) {
                const int i = tid + k2i * 512;
                const int r = 96 + (i >> 5), c4 = i & 31;
                float4 e = ((const float4*)(edge_h + (size_t)(row0 + r) * NH))[c4];
                const uint32_t o = (uint32_t)r * LDB + (uint32_t)c4 * 8u;
                *(uint2*)(sm + S_A + o) = make_uint2(pack_h2(e.x, e.y), pack_h2(e.z, e.w));
            }
            __syncthreads();

            // prefetch next tile
            {
                int nt = t + 1, ng = g;
                if (nt == 3) { nt = 0; ng = g + gridDim.x; }
                if (ng < ngroups)
                    do_prefetch(sb, edge_h, edge_idx, ar_mask, ng * 384 + nt * 128, pp ^ 1, tid);
            }

            const int*   IDXc = (const int*)(sm + S_IDX) + pp * 128;
            const float* AMc  = (const float*)(sm + S_AM) + pp * 128;

            float acc[2][4][4];

            // GEMM1 acc init: Pi + Pj + am*Ps + mb1
#pragma unroll
            for (int i = 0; i < 2; i++) {
                const int rA = m_base + i * 16 + gid;
                const int resA = (row0 + rA) / NK,  resB = (row0 + rA + 8) / NK;
                const int nbrA = IDXc[rA],          nbrB = IDXc[rA + 8];
                const float amA = AMc[rA],          amB = AMc[rA + 8];
                const float* PiA = g_Pi + (size_t)resA * NH;
                const float* PiB = g_Pi + (size_t)resB * NH;
                const float* PjA = g_Pj + (size_t)nbrA * NH;
                const float* PjB = g_Pj + (size_t)nbrB * NH;
                const float* PsA = g_Ps + (size_t)nbrA * NH;
                const float* PsB = g_Ps + (size_t)nbrB * NH;
#pragma unroll
                for (int j = 0; j < 4; j++) {
                    const int n_e = n_base + j * 8 + t4 * 2;
                    float2 piA = *(const float2*)&PiA[n_e], piB = *(const float2*)&PiB[n_e];
                    float2 pjA = *(const float2*)&PjA[n_e], pjB = *(const float2*)&PjB[n_e];
                    float2 psA = *(const float2*)&PsA[n_e], psB = *(const float2*)&PsB[n_e];
                    float2 mb = *(const float2*)&MB[n_e];
                    acc[i][j][0] = piA.x + pjA.x + amA * psA.x + mb.x;
                    acc[i][j][1] = piA.y + pjA.y + amA * psA.y + mb.y;
                    acc[i][j][2] = piB.x + pjB.x + amB * psB.x + mb.x;
                    acc[i][j][3] = piB.y + pjB.y + amB * psB.y + mb.y;
                }
            }
            // GEMM1: acc += E @ W1 (single fp16 pass)
#pragma unroll
            for (int ks = 0; ks < 8; ks++) {
                const uint32_t ko = (uint32_t)ks * 32u;
                uint32_t a[2][4], bh[4][2];
                ldm_x4(a[0][0], a[0][1], a[0][2], a[0][3], aBase + ko);
                ldm_x4(a[1][0], a[1][1], a[1][2], a[1][3], aBase + 16u * LDB + ko);
#pragma unroll
                for (int j = 0; j < 4; j++)
                    ldm_x2(bh[j][0], bh[j][1], sb + S_W1 + bOf[j] + ko);
#pragma unroll
                for (int i = 0; i < 2; i++)
#pragma unroll
                    for (int j = 0; j < 4; j++)
                        mma_f16(acc[i][j], a[i][0], a[i][1], a[i][2], a[i][3], bh[j][0], bh[j][1]);
            }
            __syncthreads();

            // epilogue 1: X1 = gelu(acc) -> A
#pragma unroll
            for (int i = 0; i < 2; i++) {
                const int m_e = m_base + i * 16 + gid;
#pragma unroll
                for (int j = 0; j < 4; j++) {
                    const int n_e = n_base + j * 8 + t4 * 2;
                    float v0 = gelu_exact(acc[i][j][0]), v1 = gelu_exact(acc[i][j][1]);
                    float v2 = gelu_exact(acc[i][j][2]), v3 = gelu_exact(acc[i][j][3]);
                    const uint32_t o0 = (uint32_t)m_e * LDB + (uint32_t)n_e * 2u;
                    const uint32_t o1 = o0 + 8u * LDB;
                    *(uint32_t*)(sm + S_A + o0) = pack_h2(v0, v1);
                    *(uint32_t*)(sm + S_A + o1) = pack_h2(v2, v3);
                }
            }
            __syncthreads();

            // GEMM2: acc = mb2 + X1 @ W2 (single fp16 pass)
#pragma unroll
            for (int i = 0; i < 2; i++)
#pragma unroll
                for (int j = 0; j < 4; j++) {
                    float2 mb = *(const float2*)&MB[128 + n_base + j * 8 + t4 * 2];
                    acc[i][j][0] = mb.x; acc[i][j][1] = mb.y;
                    acc[i][j][2] = mb.x; acc[i][j][3] = mb.y;
                }
#pragma unroll
            for (int ks = 0; ks < 8; ks++) {
                const uint32_t ko = (uint32_t)ks * 32u;
                uint32_t a[2][4], bh[4][2];
                ldm_x4(a[0][0], a[0][1], a[0][2], a[0][3], aBase + ko);
                ldm_x4(a[1][0], a[1][1], a[1][2], a[1][3], aBase + 16u * LDB + ko);
#pragma unroll
                for (int j = 0; j < 4; j++)
                    ldm_x2(bh[j][0], bh[j][1], sb + S_W2 + bOf[j] + ko);
#pragma unroll
                for (int i = 0; i < 2; i++)
#pragma unroll
                    for (int j = 0; j < 4; j++)
                        mma_f16(acc[i][j], a[i][0], a[i][1], a[i][2], a[i][3], bh[j][0], bh[j][1]);
            }

            // epilogue 2: gelu -> warp-shuffle segmented reduce -> few atomics
            {
                const int R0  = t * 128 + m_base;
                const int rl0 = R0 / NK;
                const int bb  = (rl0 + 1) * NK - R0;
#pragma unroll
                for (int j = 0; j < 4; j++) {
#pragma unroll
                    for (int p = 0; p < 2; p++) {
                        float y0 = gelu_exact(acc[0][j][p]);
                        float y1 = gelu_exact(acc[0][j][p + 2]);
                        float y2 = gelu_exact(acc[1][j][p]);
                        float y3 = gelu_exact(acc[1][j][p + 2]);
                        float s0 = 0.f, s1 = 0.f;
                        if (gid      < bb) s0 += y0; else s1 += y0;
                        if (gid + 8  < bb) s0 += y1; else s1 += y1;
                        if (gid + 16 < bb) s0 += y2; else s1 += y2;
                        if (gid + 24 < bb) s0 += y3; else s1 += y3;
#pragma unroll
                        for (int o = 4; o <= 16; o <<= 1) {
                            s0 += __shfl_xor_sync(0xffffffffu, s0, o);
                            s1 += __shfl_xor_sync(0xffffffffu, s1, o);
                        }
                        if (gid == 0) {
                            const int c = n_base + j * 8 + t4 * 2 + p;
                            atomicAdd(&SSUM[rl0 * 128 + c], s0);
                            if (bb < 32) atomicAdd(&SSUM[(rl0 + 1) * 128 + c], s1);
                        }
                    }
                }
            }
            pp ^= 1;
        }
        __syncthreads();
        for (int i = tid; i < 1024; i += 512)
            g_S[(size_t)g * 1024 + i] = SSUM[i];
    }
}

// ---------------------------------------------------------------------------
// Kernel 3: GEMM3+LN1 fp32 (proven), FFN via fp16 HMMA with W hi/lo split
// (weights exact), residual+LN2 fp32. 32 residues/CTA, 256 threads, 8 warps.
// ---------------------------------------------------------------------------
#define K3_H1  0u
#define K3_A16 16896u
#define K3_T16 25600u
#define K3_WH  58880u
#define K3_WL  93696u
#define K3_TOT 128512u
#define LDT 1040u

__global__ __launch_bounds__(256) void k3_ff(const float* __restrict__ node_h,
                                             const float* __restrict__ mW3,
                                             const float* __restrict__ mb3,
                                             const float* __restrict__ fW1,
                                             const float* __restrict__ fb1,
                                             const float* __restrict__ fW2,
                                             const float* __restrict__ fb2,
                                             const float* __restrict__ g1,
                                             const float* __restrict__ b1,
                                             const float* __restrict__ g2,
                                             const float* __restrict__ b2,
                                             float* __restrict__ out) {
    extern __shared__ char smc[];
    float* H1sh = (float*)(smc + K3_H1);
    float* Ssh  = (float*)(smc + K3_T16);
    float* Wf32 = (float*)(smc + K3_WH);
    const uint32_t sb = smem_u32(smc);

    const int tid = threadIdx.x;
    const int w   = tid >> 5, lane = tid & 31;
    const int gid = lane >> 2, t4 = lane & 3;
    const int wm  = w >> 2, wn = w & 3;
    const int m0  = blockIdx.x * 32;
    const int tc  = tid & 15, tr = tid >> 4;

    // ---- Phase A: GEMM3 (fp32) + residual + LN1 ----
    for (int i = tid; i < 4096; i += 256) ((float4*)Wf32)[i] = ((const float4*)mW3)[i];
    for (int i = tid; i < 1024; i += 256) {
        int r = i >> 5, c4 = i & 31;
        *(float4*)&Ssh[r * 132 + c4 * 4] = ((const float4*)(g_S + (size_t)(m0 + r) * NH))[c4];
    }
    __syncthreads();
    {
        float acc[2][8];
#pragma unroll
        for (int i = 0; i < 2; i++)
#pragma unroll
            for (int j = 0; j < 8; j++)
                acc[i][j] = 48.f * mb3[(j < 4 ? tc * 4 + j : 64 + tc * 4 + j - 4)];
#pragma unroll 4
        for (int kk = 0; kk < 128; kk++) {
            float4 b0 = *(const float4*)&Wf32[kk * 128 + tc * 4];
            float4 b1v = *(const float4*)&Wf32[kk * 128 + 64 + tc * 4];
#pragma unroll
            for (int i = 0; i < 2; i++) {
                float a = Ssh[(tr * 2 + i) * 132 + kk];
                acc[i][0] = fmaf(a, b0.x, acc[i][0]); acc[i][1] = fmaf(a, b0.y, acc[i][1]);
                acc[i][2] = fmaf(a, b0.z, acc[i][2]); acc[i][3] = fmaf(a, b0.w, acc[i][3]);
                acc[i][4] = fmaf(a, b1v.x, acc[i][4]); acc[i][5] = fmaf(a, b1v.y, acc[i][5]);
                acc[i][6] = fmaf(a, b1v.z, acc[i][6]); acc[i][7] = fmaf(a, b1v.w, acc[i][7]);
            }
        }
#pragma unroll
        for (int i = 0; i < 2; i++) {
            const float* nrow = node_h + (size_t)(m0 + tr * 2 + i) * NH;
            float4 n0 = *(const float4*)&nrow[tc * 4];
            float4 n1 = *(const float4*)&nrow[64 + tc * 4];
            float* hrow = &H1sh[(tr * 2 + i) * 132];
            hrow[tc * 4 + 0] = acc[i][0] + n0.x; hrow[tc * 4 + 1] = acc[i][1] + n0.y;
            hrow[tc * 4 + 2] = acc[i][2] + n0.z; hrow[tc * 4 + 3] = acc[i][3] + n0.w;
            hrow[64 + tc * 4 + 0] = acc[i][4] + n1.x; hrow[64 + tc * 4 + 1] = acc[i][5] + n1.y;
            hrow[64 + tc * 4 + 2] = acc[i][6] + n1.z; hrow[64 + tc * 4 + 3] = acc[i][7] + n1.w;
        }
    }
    __syncthreads();

    for (int r = w; r < 32; r += 8) {
        const int c0 = lane * 4;
        float v0 = H1sh[r * 132 + c0], v1 = H1sh[r * 132 + c0 + 1];
        float v2 = H1sh[r * 132 + c0 + 2], v3 = H1sh[r * 132 + c0 + 3];
        float s = v0 + v1 + v2 + v3;
#pragma unroll
        for (int o = 16; o; o >>= 1) s += __shfl_xor_sync(0xffffffffu, s, o);
        float mu = s * (1.f / 128.f);
        float d0 = v0 - mu, d1 = v1 - mu, d2 = v2 - mu, d3 = v3 - mu;
        float q = d0 * d0 + d1 * d1 + d2 * d2 + d3 * d3;
#pragma unroll
        for (int o = 16; o; o >>= 1) q += __shfl_xor_sync(0xffffffffu, q, o);
        float rs = rsqrtf(q * (1.f / 128.f) + 1e-5f);
        H1sh[r * 132 + c0]     = d0 * rs * g1[c0]     + b1[c0];
        H1sh[r * 132 + c0 + 1] = d1 * rs * g1[c0 + 1] + b1[c0 + 1];
        H1sh[r * 132 + c0 + 2] = d2 * rs * g1[c0 + 2] + b1[c0 + 2];
        H1sh[r * 132 + c0 + 3] = d3 * rs * g1[c0 + 3] + b1[c0 + 3];
    }
    __syncthreads();

    // convert H1 -> A16 fp16 operand
    {
        const int r = tid >> 3, c0 = (tid & 7) * 16;
        const float* hrow = &H1sh[r * 132 + c0];
        uint32_t pk[8];
#pragma unroll
        for (int j = 0; j < 8; j++) pk[j] = pack_h2(hrow[j * 2], hrow[j * 2 + 1]);
        char* dst = smc + K3_A16 + (uint32_t)r * LDB + (uint32_t)c0 * 2u;
        *(uint4*)dst        = make_uint4(pk[0], pk[1], pk[2], pk[3]);
        *(uint4*)(dst + 16) = make_uint4(pk[4], pk[5], pk[6], pk[7]);
    }

    const uint32_t aAddr1 = sb + K3_A16 + (uint32_t)(wm * 16 + (lane & 15)) * LDB
                          + (uint32_t)((lane >> 4) * 16);
    const uint32_t aAddr2 = sb + K3_T16 + (uint32_t)(wm * 16 + (lane & 15)) * LDT
                          + (uint32_t)((lane >> 4) * 16);
    const uint32_t b_off = (uint32_t)(lane & 7) * LDB + (uint32_t)(((lane >> 3) & 1) * 16);
    uint32_t bOf[4];
#pragma unroll
    for (int j = 0; j < 4; j++)
        bOf[j] = (uint32_t)(wn * 32 + j * 8) * LDB + b_off;

    // ---- Phase B: FF1 (128 -> 512) in 4 N-chunks, W split hi/lo ----
    for (int nc = 0; nc < 4; nc++) {
        __syncthreads();
        for (int idx = tid; idx < 16384; idx += 256) {
            const int n = idx & 127, k = idx >> 7;
            float wv = fW1[(size_t)k * 512 + nc * 128 + n];
            __half h = __float2half_rn(wv);
            __half l = __float2half_rn(wv - __half2float(h));
            const uint32_t o = (uint32_t)n * LDB + (uint32_t)k * 2u;
            *(__half*)(smc + K3_WH + o) = h;
            *(__half*)(smc + K3_WL + o) = l;
        }
        __syncthreads();
        float acc[4][4];
#pragma unroll
        for (int j = 0; j < 4; j++) {
            float2 fb = *(const float2*)&fb1[nc * 128 + wn * 32 + j * 8 + t4 * 2];
            acc[j][0] = fb.x; acc[j][1] = fb.y; acc[j][2] = fb.x; acc[j][3] = fb.y;
        }
#pragma unroll
        for (int ks = 0; ks < 8; ks++) {
            const uint32_t ko = (uint32_t)ks * 32u;
            uint32_t a[4], bh[4][2], bl[4][2];
            ldm_x4(a[0], a[1], a[2], a[3], aAddr1 + ko);
#pragma unroll
            for (int j = 0; j < 4; j++) {
                ldm_x2(bh[j][0], bh[j][1], sb + K3_WH + bOf[j] + ko);
                ldm_x2(bl[j][0], bl[j][1], sb + K3_WL + bOf[j] + ko);
            }
#pragma unroll
            for (int j = 0; j < 4; j++) {
                mma_f16(acc[j], a[0], a[1], a[2], a[3], bh[j][0], bh[j][1]);
                mma_f16(acc[j], a[0], a[1], a[2], a[3], bl[j][0], bl[j][1]);
            }
        }
#pragma unroll
        for (int j = 0; j < 4; j++) {
            const int r0 = wm * 16 + gid;
            const int cg = nc * 128 + wn * 32 + j * 8 + t4 * 2;
            *(uint32_t*)(smc + K3_T16 + (uint32_t)r0 * LDT + (uint32_t)cg * 2u) =
                pack_h2(gelu_exact(acc[j][0]), gelu_exact(acc[j][1]));
            *(uint32_t*)(smc + K3_T16 + (uint32_t)(r0 + 8) * LDT + (uint32_t)cg * 2u) =
                pack_h2(gelu_exact(acc[j][2]), gelu_exact(acc[j][3]));
        }
    }

    // ---- Phase C: FF2 (512 -> 128) in 4 K-chunks, W split hi/lo ----
    float acc2[4][4];
#pragma unroll
    for (int j = 0; j < 4; j++) {
        float2 fb = *(const float2*)&fb2[wn * 32 + j * 8 + t4 * 2];
        acc2[j][0] = fb.x; acc2[j][1] = fb.y; acc2[j][2] = fb.x; acc2[j][3] = fb.y;
    }
    for (int kc = 0; kc < 4; kc++) {
        __syncthreads();
        for (int idx = tid; idx < 16384; idx += 256) {
            const int n = idx & 127, k = idx >> 7;
            float wv = fW2[(size_t)(kc * 128 + k) * 128 + n];
            __half h = __float2half_rn(wv);
            __half l = __float2half_rn(wv - __half2float(h));
            const uint32_t o = (uint32_t)n * LDB + (uint32_t)k * 2u;
            *(__half*)(smc + K3_WH + o) = h;
            *(__half*)(smc + K3_WL + o) = l;
        }
        __syncthreads();
#pragma unroll
        for (int ks = 0; ks < 8; ks++) {
            const uint32_t ko = (uint32_t)ks * 32u;
            uint32_t a[4], bh[4][2], bl[4][2];
            ldm_x4(a[0], a[1], a[2], a[3], aAddr2 + (uint32_t)kc * 256u + ko);
#pragma unroll
            for (int j = 0; j < 4; j++) {
                ldm_x2(bh[j][0], bh[j][1], sb + K3_WH + bOf[j] + ko);
                ldm_x2(bl[j][0], bl[j][1], sb + K3_WL + bOf[j] + ko);
            }
#pragma unroll
            for (int j = 0; j < 4; j++) {
                mma_f16(acc2[j], a[0], a[1], a[2], a[3], bh[j][0], bh[j][1]);
                mma_f16(acc2[j], a[0], a[1], a[2], a[3], bl[j][0], bl[j][1]);
            }
        }
    }

    // ---- Phase D: residual + LN2 -> out ----
    __syncthreads();
    float* Vsh = (float*)(smc + K3_T16);
#pragma unroll
    for (int j = 0; j < 4; j++) {
        const int r0 = wm * 16 + gid, r1 = r0 + 8;
        const int c = wn * 32 + j * 8 + t4 * 2;
        Vsh[r0 * 132 + c]     = H1sh[r0 * 132 + c]     + acc2[j][0];
        Vsh[r0 * 132 + c + 1] = H1sh[r0 * 132 + c + 1] + acc2[j][1];
        Vsh[r1 * 132 + c]     = H1sh[r1 * 132 + c]     + acc2[j][2];
        Vsh[r1 * 132 + c + 1] = H1sh[r1 * 132 + c + 1] + acc2[j][3];
    }
    __syncthreads();
    for (int r = w; r < 32; r += 8) {
        const int c0 = lane * 4;
        float v0 = Vsh[r * 132 + c0], v1 = Vsh[r * 132 + c0 + 1];
        float v2 = Vsh[r * 132 + c0 + 2], v3 = Vsh[r * 132 + c0 + 3];
        float s = v0 + v1 + v2 + v3;
#pragma unroll
        for (int o = 16; o; o >>= 1) s += __shfl_xor_sync(0xffffffffu, s, o);
        float mu = s * (1.f / 128.f);
        float d0 = v0 - mu, d1 = v1 - mu, d2 = v2 - mu, d3 = v3 - mu;
        float q = d0 * d0 + d1 * d1 + d2 * d2 + d3 * d3;
#pragma unroll
        for (int o = 16; o; o >>= 1) q += __shfl_xor_sync(0xffffffffu, q, o);
        float rs = rsqrtf(q * (1.f / 128.f) + 1e-5f);
        float4 o4;
        o4.x = d0 * rs * g2[c0]     + b2[c0];
        o4.y = d1 * rs * g2[c0 + 1] + b2[c0 + 1];
        o4.z = d2 * rs * g2[c0 + 2] + b2[c0 + 2];
        o4.w = d3 * rs * g2[c0 + 3] + b2[c0 + 3];
        *(float4*)&out[(size_t)(m0 + r) * NH + c0] = o4;
    }
}

// ---------------------------------------------------------------------------
extern "C" void kernel_launch(void* const* d_in, const int* in_sizes, int n_in,
                              void* d_out, int out_size) {
    const float* node_h   = (const float*)d_in[0];
    const float* edge_h   = (const float*)d_in[1];
    const int*   edge_idx = (const int*)d_in[2];
    const float* seq_emb  = (const float*)d_in[3];
    const float* ar_mask  = (const float*)d_in[4];
    const float* mW1 = (const float*)d_in[5];
    const float* mb1 = (const float*)d_in[6];
    const float* mW2 = (const float*)d_in[7];
    const float* mb2 = (const float*)d_in[8];
    const float* mW3 = (const float*)d_in[9];
    const float* mb3 = (const float*)d_in[10];
    const float* fW1 = (const float*)d_in[11];
    const float* fb1 = (const float*)d_in[12];
    const float* fW2 = (const float*)d_in[13];
    const float* fb2 = (const float*)d_in[14];
    const float* g1  = (const float*)d_in[15];
    const float* b1  = (const float*)d_in[16];
    const float* g2  = (const float*)d_in[17];
    const float* b2  = (const float*)d_in[18];
    float* out = (float*)d_out;

    int dev = 0;
    cudaGetDevice(&dev);
    int nsm = 148;
    cudaDeviceGetAttribute(&nsm, cudaDevAttrMultiProcessorCount, dev);

    const size_t smem1 = (size_t)(16384 + 64 * 132) * sizeof(float);

    cudaFuncSetAttribute(k1_pre, cudaFuncAttributeMaxDynamicSharedMemorySize, (int)smem1);
    cudaFuncSetAttribute(k2_msg, cudaFuncAttributeMaxDynamicSharedMemorySize, (int)S_K2TOT);
    cudaFuncSetAttribute(k3_ff,  cudaFuncAttributeMaxDynamicSharedMemorySize, (int)K3_TOT);

    dim3 grid1(NRES / 64, 3);
    k1_pre<<<grid1, 256, smem1>>>(node_h, seq_emb, mW1);

    const int ngroups = NRES / 8;
    k2_msg<<<nsm, 512, S_K2TOT>>>(edge_h, edge_idx, ar_mask,
                                  mW1, mb1, mW2, mb2, ngroups);

    k3_ff<<<NRES / 32, 256, K3_TOT>>>(node_h, mW3, mb3, fW1, fb1, fW2, fb2,
                                      g1, b1, g2, b2, out);
}

// round 11
// speedup vs baseline: 1.2190x; 1.2190x over previous
#include <cuda_runtime.h>
#include <cuda_fp16.h>
#include <math.h>
#include <stdint.h>

#define NRES 8192
#define NK   48
#define NH   128

__device__ float g_Pi[NRES * NH];
__device__ float g_Pj[NRES * NH];
__device__ float g_Ps[NRES * NH];
__device__ float g_S [NRES * NH];

__device__ __forceinline__ float gelu_exact(float x) {
    return 0.5f * x * (1.0f + erff(x * 0.7071067811865475f));
}
__device__ __forceinline__ uint32_t smem_u32(const void* p) {
    uint32_t a;
    asm("{ .reg .u64 t; cvta.to.shared.u64 t, %1; cvt.u32.u64 %0, t; }" : "=r"(a) : "l"(p));
    return a;
}
__device__ __forceinline__ uint32_t pack_h2(float a, float b) {
    __half2 h = __floats2half2_rn(a, b);
    return *reinterpret_cast<uint32_t*>(&h);
}
__device__ __forceinline__ void ldm_x4(uint32_t& r0, uint32_t& r1, uint32_t& r2, uint32_t& r3, uint32_t a) {
    asm volatile("ldmatrix.sync.aligned.m8n8.x4.shared.b16 {%0,%1,%2,%3}, [%4];"
                 : "=r"(r0), "=r"(r1), "=r"(r2), "=r"(r3) : "r"(a));
}
__device__ __forceinline__ void ldm_x2(uint32_t& r0, uint32_t& r1, uint32_t a) {
    asm volatile("ldmatrix.sync.aligned.m8n8.x2.shared.b16 {%0,%1}, [%2];"
                 : "=r"(r0), "=r"(r1) : "r"(a));
}
__device__ __forceinline__ void mma_f16(float* c, uint32_t a0, uint32_t a1, uint32_t a2, uint32_t a3,
                                        uint32_t b0, uint32_t b1) {
    asm volatile("mma.sync.aligned.m16n8k16.row.col.f32.f16.f16.f32 "
                 "{%0,%1,%2,%3}, {%4,%5,%6,%7}, {%8,%9}, {%0,%1,%2,%3};"
                 : "+f"(c[0]), "+f"(c[1]), "+f"(c[2]), "+f"(c[3])
                 : "r"(a0), "r"(a1), "r"(a2), "r"(a3), "r"(b0), "r"(b1));
}

// ---------------------------------------------------------------------------
// Kernel 1: Pi/Pj/Ps projections (fp32, conflict-free columns) — proven
// ---------------------------------------------------------------------------
__global__ __launch_bounds__(256) void k1_pre(const float* __restrict__ node_h,
                                              const float* __restrict__ seq_emb,
                                              const float* __restrict__ mW1) {
    extern __shared__ float sm1[];
    float* Wsh = sm1;
    float* Ash = sm1 + 16384;
    const int tid   = threadIdx.x;
    const int which = blockIdx.y;
    const float* A    = (which == 2) ? seq_emb : node_h;
    const float* Wsrc = mW1 + (size_t)(which == 0 ? 0 : (which == 1 ? 128 : 384)) * NH;
    float* out = (which == 0) ? g_Pi : (which == 1 ? g_Pj : g_Ps);

    for (int i = tid; i < 4096; i += 256) ((float4*)Wsh)[i] = ((const float4*)Wsrc)[i];
    const int m0 = blockIdx.x * 64;
    for (int i = tid; i < 2048; i += 256) {
        int r = i >> 5, c4 = i & 31;
        *(float4*)&Ash[r * 132 + c4 * 4] = ((const float4*)(A + (size_t)(m0 + r) * NH))[c4];
    }
    __syncthreads();
    const int tc = tid & 15, tr = tid >> 4;
    float acc[4][8];
#pragma unroll
    for (int i = 0; i < 4; i++)
#pragma unroll
        for (int j = 0; j < 8; j++) acc[i][j] = 0.f;
#pragma unroll 4
    for (int kk = 0; kk < 128; kk++) {
        float4 b0 = *(const float4*)&Wsh[kk * 128 + tc * 4];
        float4 b1 = *(const float4*)&Wsh[kk * 128 + 64 + tc * 4];
#pragma unroll
        for (int i = 0; i < 4; i++) {
            float a = Ash[(tr * 4 + i) * 132 + kk];
            acc[i][0] = fmaf(a, b0.x, acc[i][0]); acc[i][1] = fmaf(a, b0.y, acc[i][1]);
            acc[i][2] = fmaf(a, b0.z, acc[i][2]); acc[i][3] = fmaf(a, b0.w, acc[i][3]);
            acc[i][4] = fmaf(a, b1.x, acc[i][4]); acc[i][5] = fmaf(a, b1.y, acc[i][5]);
            acc[i][6] = fmaf(a, b1.z, acc[i][6]); acc[i][7] = fmaf(a, b1.w, acc[i][7]);
        }
    }
#pragma unroll
    for (int i = 0; i < 4; i++) {
        size_t r = (size_t)(m0 + tr * 4 + i) * NH;
        *(float4*)&out[r + tc * 4]      = make_float4(acc[i][0], acc[i][1], acc[i][2], acc[i][3]);
        *(float4*)&out[r + 64 + tc * 4] = make_float4(acc[i][4], acc[i][5], acc[i][6], acc[i][7]);
    }
}

// ---------------------------------------------------------------------------
// Kernel 2: per-edge MLP, single-pass fp16 HMMA (round-9 version, kept)
// ---------------------------------------------------------------------------
#define LDB 272u
#define S_W1  0u
#define S_W2  34816u
#define S_A   69632u
#define S_STG 104448u
#define S_SSUM 153600u
#define S_IDX 157696u
#define S_AM  158720u
#define S_MB  159744u
#define S_K2TOT 160768u

__device__ __forceinline__ void do_prefetch(uint32_t sb, const float* edge_h,
                                            const int* edge_idx, const float* ar_mask,
                                            int row0, int pp, int tid) {
    const char* src = (const char*)(edge_h + (size_t)row0 * NH);
#pragma unroll
    for (int k = 0; k < 6; k++) {
        uint32_t off = (uint32_t)(tid + k * 512) * 16u;
        asm volatile("cp.async.cg.shared.global [%0], [%1], 16;"
                     :: "r"(sb + S_STG + off), "l"(src + off));
    }
    if (tid < 128)
        asm volatile("cp.async.ca.shared.global [%0], [%1], 4;"
                     :: "r"(sb + S_IDX + (uint32_t)pp * 512u + (uint32_t)tid * 4u),
                        "l"(edge_idx + row0 + tid));
    else if (tid < 256)
        asm volatile("cp.async.ca.shared.global [%0], [%1], 4;"
                     :: "r"(sb + S_AM + (uint32_t)pp * 512u + (uint32_t)(tid - 128) * 4u),
                        "l"(ar_mask + row0 + (tid - 128)));
    asm volatile("cp.async.commit_group;" ::: "memory");
}

__global__ __launch_bounds__(512) void k2_msg(const float* __restrict__ edge_h,
                                              const int*   __restrict__ edge_idx,
                                              const float* __restrict__ ar_mask,
                                              const float* __restrict__ mW1,
                                              const float* __restrict__ mb1,
                                              const float* __restrict__ mW2,
                                              const float* __restrict__ mb2,
                                              int ngroups) {
    extern __shared__ char sm[];
    const int tid  = threadIdx.x;
    const int w    = tid >> 5, lane = tid & 31;
    const int gid  = lane >> 2, t4 = lane & 3;
    const int wm   = w >> 2, wn = w & 3;
    const int m_base = wm * 32, n_base = wn * 32;
    const uint32_t sb = smem_u32(sm);

    float* SSUM = (float*)(sm + S_SSUM);
    float* MB   = (float*)(sm + S_MB);
    float* STG  = (float*)(sm + S_STG);

    if (tid < 128) MB[tid] = mb1[tid];
    else if (tid < 256) MB[tid] = mb2[tid - 128];

    // stage W1c^T / W2^T as fp16 (coalesced reads)
    for (int idx = tid; idx < 16384; idx += 512) {
        const int n = idx & 127, k = idx >> 7;
        float w1 = mW1[(size_t)(256 + k) * NH + n];
        float w2 = mW2[(size_t)k * NH + n];
        const uint32_t o = (uint32_t)n * LDB + (uint32_t)k * 2u;
        *(__half*)(sm + S_W1 + o) = __float2half_rn(w1);
        *(__half*)(sm + S_W2 + o) = __float2half_rn(w2);
    }

    const uint32_t aBase = sb + S_A + (uint32_t)(m_base + (lane & 15)) * LDB
                         + (uint32_t)((lane >> 4) * 16);
    const uint32_t b_off = (uint32_t)(lane & 7) * LDB + (uint32_t)(((lane >> 3) & 1) * 16);
    uint32_t bOf[4];
#pragma unroll
    for (int j = 0; j < 4; j++)
        bOf[j] = (uint32_t)(n_base + j * 8) * LDB + b_off;

    int pp = 0;
    if ((int)blockIdx.x < ngroups)
        do_prefetch(sb, edge_h, edge_idx, ar_mask, blockIdx.x * 384, 0, tid);

    for (int g = blockIdx.x; g < ngroups; g += gridDim.x) {
        for (int t = 0; t < 3; t++) {
            const int row0 = g * 384 + t * 128;
            asm volatile("cp.async.wait_group 0;" ::: "memory");
            __syncthreads();
            if (t == 0)
                for (int i = tid; i < 1024; i += 512) SSUM[i] = 0.f;

            // staged rows 0-95 -> A fp16
#pragma unroll
            for (int k2i = 0; k2i < 6; k2i++) {
                const int i = tid + k2i * 512;
                const int r = i >> 5, c4 = i & 31;
                float4 e = *(const float4*)((const char*)STG + (size_t)i * 16);
                const uint32_t o = (uint32_t)r * LDB + (uint32_t)c4 * 8u;
                *(uint2*)(sm + S_A + o) = make_uint2(pack_h2(e.x, e.y), pack_h2(e.z, e.w));
            }
            // direct rows 96-127
#pragma unroll
            for (int k2i = 0; k2i < 2; k2i++) {
                const int i = tid + k2i * 512;
                const int r = 96 + (i >> 5), c4 = i & 31;
                float4 e = ((const float4*)(edge_h + (size_t)(row0 + r) * NH))[c4];
                const uint32_t o = (uint32_t)r * LDB + (uint32_t)c4 * 8u;
                *(uint2*)(sm + S_A + o) = make_uint2(pack_h2(e.x, e.y), pack_h2(e.z, e.w));
            }
            __syncthreads();

            // prefetch next tile
            {
                int nt = t + 1, ng = g;
                if (nt == 3) { nt = 0; ng = g + gridDim.x; }
                if (ng < ngroups)
                    do_prefetch(sb, edge_h, edge_idx, ar_mask, ng * 384 + nt * 128, pp ^ 1, tid);
            }

            const int*   IDXc = (const int*)(sm + S_IDX) + pp * 128;
            const float* AMc  = (const float*)(sm + S_AM) + pp * 128;

            float acc[2][4][4];

            // GEMM1 acc init: Pi + Pj + am*Ps + mb1
#pragma unroll
            for (int i = 0; i < 2; i++) {
                const int rA = m_base + i * 16 + gid;
                const int resA = (row0 + rA) / NK,  resB = (row0 + rA + 8) / NK;
                const int nbrA = IDXc[rA],          nbrB = IDXc[rA + 8];
                const float amA = AMc[rA],          amB = AMc[rA + 8];
                const float* PiA = g_Pi + (size_t)resA * NH;
                const float* PiB = g_Pi + (size_t)resB * NH;
                const float* PjA = g_Pj + (size_t)nbrA * NH;
                const float* PjB = g_Pj + (size_t)nbrB * NH;
                const float* PsA = g_Ps + (size_t)nbrA * NH;
                const float* PsB = g_Ps + (size_t)nbrB * NH;
#pragma unroll
                for (int j = 0; j < 4; j++) {
                    const int n_e = n_base + j * 8 + t4 * 2;
                    float2 piA = *(const float2*)&PiA[n_e], piB = *(const float2*)&PiB[n_e];
                    float2 pjA = *(const float2*)&PjA[n_e], pjB = *(const float2*)&PjB[n_e];
                    float2 psA = *(const float2*)&PsA[n_e], psB = *(const float2*)&PsB[n_e];
                    float2 mb = *(const float2*)&MB[n_e];
                    acc[i][j][0] = piA.x + pjA.x + amA * psA.x + mb.x;
                    acc[i][j][1] = piA.y + pjA.y + amA * psA.y + mb.y;
                    acc[i][j][2] = piB.x + pjB.x + amB * psB.x + mb.x;
                    acc[i][j][3] = piB.y + pjB.y + amB * psB.y + mb.y;
                }
            }
            // GEMM1: acc += E @ W1 (single fp16 pass)
#pragma unroll
            for (int ks = 0; ks < 8; ks++) {
                const uint32_t ko = (uint32_t)ks * 32u;
                uint32_t a[2][4], bh[4][2];
                ldm_x4(a[0][0], a[0][1], a[0][2], a[0][3], aBase + ko);
                ldm_x4(a[1][0], a[1][1], a[1][2], a[1][3], aBase + 16u * LDB + ko);
#pragma unroll
                for (int j = 0; j < 4; j++)
                    ldm_x2(bh[j][0], bh[j][1], sb + S_W1 + bOf[j] + ko);
#pragma unroll
                for (int i = 0; i < 2; i++)
#pragma unroll
                    for (int j = 0; j < 4; j++)
                        mma_f16(acc[i][j], a[i][0], a[i][1], a[i][2], a[i][3], bh[j][0], bh[j][1]);
            }
            __syncthreads();

            // epilogue 1: X1 = gelu(acc) -> A
#pragma unroll
            for (int i = 0; i < 2; i++) {
                const int m_e = m_base + i * 16 + gid;
#pragma unroll
                for (int j = 0; j < 4; j++) {
                    const int n_e = n_base + j * 8 + t4 * 2;
                    float v0 = gelu_exact(acc[i][j][0]), v1 = gelu_exact(acc[i][j][1]);
                    float v2 = gelu_exact(acc[i][j][2]), v3 = gelu_exact(acc[i][j][3]);
                    const uint32_t o0 = (uint32_t)m_e * LDB + (uint32_t)n_e * 2u;
                    const uint32_t o1 = o0 + 8u * LDB;
                    *(uint32_t*)(sm + S_A + o0) = pack_h2(v0, v1);
                    *(uint32_t*)(sm + S_A + o1) = pack_h2(v2, v3);
                }
            }
            __syncthreads();

            // GEMM2: acc = mb2 + X1 @ W2 (single fp16 pass)
#pragma unroll
            for (int i = 0; i < 2; i++)
#pragma unroll
                for (int j = 0; j < 4; j++) {
                    float2 mb = *(const float2*)&MB[128 + n_base + j * 8 + t4 * 2];
                    acc[i][j][0] = mb.x; acc[i][j][1] = mb.y;
                    acc[i][j][2] = mb.x; acc[i][j][3] = mb.y;
                }
#pragma unroll
            for (int ks = 0; ks < 8; ks++) {
                const uint32_t ko = (uint32_t)ks * 32u;
                uint32_t a[2][4], bh[4][2];
                ldm_x4(a[0][0], a[0][1], a[0][2], a[0][3], aBase + ko);
                ldm_x4(a[1][0], a[1][1], a[1][2], a[1][3], aBase + 16u * LDB + ko);
#pragma unroll
                for (int j = 0; j < 4; j++)
                    ldm_x2(bh[j][0], bh[j][1], sb + S_W2 + bOf[j] + ko);
#pragma unroll
                for (int i = 0; i < 2; i++)
#pragma unroll
                    for (int j = 0; j < 4; j++)
                        mma_f16(acc[i][j], a[i][0], a[i][1], a[i][2], a[i][3], bh[j][0], bh[j][1]);
            }

            // epilogue 2: gelu -> warp-shuffle segmented reduce -> few atomics
            {
                const int R0  = t * 128 + m_base;
                const int rl0 = R0 / NK;
                const int bb  = (rl0 + 1) * NK - R0;
#pragma unroll
                for (int j = 0; j < 4; j++) {
#pragma unroll
                    for (int p = 0; p < 2; p++) {
                        float y0 = gelu_exact(acc[0][j][p]);
                        float y1 = gelu_exact(acc[0][j][p + 2]);
                        float y2 = gelu_exact(acc[1][j][p]);
                        float y3 = gelu_exact(acc[1][j][p + 2]);
                        float s0 = 0.f, s1 = 0.f;
                        if (gid      < bb) s0 += y0; else s1 += y0;
                        if (gid + 8  < bb) s0 += y1; else s1 += y1;
                        if (gid + 16 < bb) s0 += y2; else s1 += y2;
                        if (gid + 24 < bb) s0 += y3; else s1 += y3;
#pragma unroll
                        for (int o = 4; o <= 16; o <<= 1) {
                            s0 += __shfl_xor_sync(0xffffffffu, s0, o);
                            s1 += __shfl_xor_sync(0xffffffffu, s1, o);
                        }
                        if (gid == 0) {
                            const int c = n_base + j * 8 + t4 * 2 + p;
                            atomicAdd(&SSUM[rl0 * 128 + c], s0);
                            if (bb < 32) atomicAdd(&SSUM[(rl0 + 1) * 128 + c], s1);
                        }
                    }
                }
            }
            pp ^= 1;
        }
        __syncthreads();
        for (int i = tid; i < 1024; i += 512)
            g_S[(size_t)g * 1024 + i] = SSUM[i];
    }
}

// ---------------------------------------------------------------------------
// Kernel 3: agg = S@W3 + 48*mb3; LN1; FFN; LN2 — round-7 fp32 version (proven)
// ---------------------------------------------------------------------------
__global__ __launch_bounds__(256) void k3_ff(const float* __restrict__ node_h,
                                             const float* __restrict__ mW3,
                                             const float* __restrict__ mb3,
                                             const float* __restrict__ fW1,
                                             const float* __restrict__ fb1,
                                             const float* __restrict__ fW2,
                                             const float* __restrict__ fb2,
                                             const float* __restrict__ g1,
                                             const float* __restrict__ b1,
                                             const float* __restrict__ g2,
                                             const float* __restrict__ b2,
                                             float* __restrict__ out) {
    extern __shared__ float sm3[];
    float* H1sh = sm3;
    float* Tsh  = sm3 + 32 * 132;
    float* Wsh  = sm3 + 32 * 132 + 32 * 516;

    const int tid = threadIdx.x;
    const int wid = tid >> 5, lane = tid & 31;
    const int m0  = blockIdx.x * 32;
    const int tc = tid & 15, tr = tid >> 4;

    for (int i = tid; i < 4096; i += 256) ((float4*)Wsh)[i] = ((const float4*)mW3)[i];
    for (int i = tid; i < 1024; i += 256) {
        int r = i >> 5, c4 = i & 31;
        *(float4*)&Tsh[r * 132 + c4 * 4] = ((const float4*)(g_S + (size_t)(m0 + r) * NH))[c4];
    }
    __syncthreads();

    {
        float acc[2][8];
#pragma unroll
        for (int i = 0; i < 2; i++)
#pragma unroll
            for (int j = 0; j < 8; j++)
                acc[i][j] = 48.f * mb3[(j < 4 ? tc * 4 + j : 64 + tc * 4 + j - 4)];
#pragma unroll 4
        for (int kk = 0; kk < 128; kk++) {
            float4 b0 = *(const float4*)&Wsh[kk * 128 + tc * 4];
            float4 b1v = *(const float4*)&Wsh[kk * 128 + 64 + tc * 4];
#pragma unroll
            for (int i = 0; i < 2; i++) {
                float a = Tsh[(tr * 2 + i) * 132 + kk];
                acc[i][0] = fmaf(a, b0.x, acc[i][0]); acc[i][1] = fmaf(a, b0.y, acc[i][1]);
                acc[i][2] = fmaf(a, b0.z, acc[i][2]); acc[i][3] = fmaf(a, b0.w, acc[i][3]);
                acc[i][4] = fmaf(a, b1v.x, acc[i][4]); acc[i][5] = fmaf(a, b1v.y, acc[i][5]);
                acc[i][6] = fmaf(a, b1v.z, acc[i][6]); acc[i][7] = fmaf(a, b1v.w, acc[i][7]);
            }
        }
#pragma unroll
        for (int i = 0; i < 2; i++) {
            const float* nrow = node_h + (size_t)(m0 + tr * 2 + i) * NH;
            float4 n0 = *(const float4*)&nrow[tc * 4];
            float4 n1 = *(const float4*)&nrow[64 + tc * 4];
            float* hrow = &H1sh[(tr * 2 + i) * 132];
            hrow[tc * 4 + 0] = acc[i][0] + n0.x; hrow[tc * 4 + 1] = acc[i][1] + n0.y;
            hrow[tc * 4 + 2] = acc[i][2] + n0.z; hrow[tc * 4 + 3] = acc[i][3] + n0.w;
            hrow[64 + tc * 4 + 0] = acc[i][4] + n1.x; hrow[64 + tc * 4 + 1] = acc[i][5] + n1.y;
            hrow[64 + tc * 4 + 2] = acc[i][6] + n1.z; hrow[64 + tc * 4 + 3] = acc[i][7] + n1.w;
        }
    }
    __syncthreads();

    for (int r = wid; r < 32; r += 8) {
        const int c0 = lane * 4;
        float v0 = H1sh[r * 132 + c0], v1 = H1sh[r * 132 + c0 + 1];
        float v2 = H1sh[r * 132 + c0 + 2], v3 = H1sh[r * 132 + c0 + 3];
        float s = v0 + v1 + v2 + v3;
#pragma unroll
        for (int o = 16; o; o >>= 1) s += __shfl_xor_sync(0xffffffffu, s, o);
        float mu = s * (1.f / 128.f);
        float d0 = v0 - mu, d1 = v1 - mu, d2 = v2 - mu, d3 = v3 - mu;
        float q = d0 * d0 + d1 * d1 + d2 * d2 + d3 * d3;
#pragma unroll
        for (int o = 16; o; o >>= 1) q += __shfl_xor_sync(0xffffffffu, q, o);
        float rs = rsqrtf(q * (1.f / 128.f) + 1e-5f);
        H1sh[r * 132 + c0]     = d0 * rs * g1[c0]     + b1[c0];
        H1sh[r * 132 + c0 + 1] = d1 * rs * g1[c0 + 1] + b1[c0 + 1];
        H1sh[r * 132 + c0 + 2] = d2 * rs * g1[c0 + 2] + b1[c0 + 2];
        H1sh[r * 132 + c0 + 3] = d3 * rs * g1[c0 + 3] + b1[c0 + 3];
    }

    for (int nc = 0; nc < 4; nc++) {
        __syncthreads();
        for (int i = tid; i < 4096; i += 256) {
            int k = i >> 5, c4 = i & 31;
            ((float4*)&Wsh[k * 128])[c4] = ((const float4*)&fW1[(size_t)k * 512 + nc * 128])[c4];
        }
        __syncthreads();
        float acc[2][8];
#pragma unroll
        for (int i = 0; i < 2; i++)
#pragma unroll
            for (int j = 0; j < 8; j++)
                acc[i][j] = fb1[nc * 128 + (j < 4 ? tc * 4 + j : 64 + tc * 4 + j - 4)];
#pragma unroll 4
        for (int kk = 0; kk < 128; kk++) {
            float4 b0 = *(const float4*)&Wsh[kk * 128 + tc * 4];
            float4 b1v = *(const float4*)&Wsh[kk * 128 + 64 + tc * 4];
#pragma unroll
            for (int i = 0; i < 2; i++) {
                float a = H1sh[(tr * 2 + i) * 132 + kk];
                acc[i][0] = fmaf(a, b0.x, acc[i][0]); acc[i][1] = fmaf(a, b0.y, acc[i][1]);
                acc[i][2] = fmaf(a, b0.z, acc[i][2]); acc[i][3] = fmaf(a, b0.w, acc[i][3]);
                acc[i][4] = fmaf(a, b1v.x, acc[i][4]); acc[i][5] = fmaf(a, b1v.y, acc[i][5]);
                acc[i][6] = fmaf(a, b1v.z, acc[i][6]); acc[i][7] = fmaf(a, b1v.w, acc[i][7]);
            }
        }
#pragma unroll
        for (int i = 0; i < 2; i++) {
            float* trow = &Tsh[(tr * 2 + i) * 516 + nc * 128];
#pragma unroll
            for (int j = 0; j < 4; j++) trow[tc * 4 + j]      = gelu_exact(acc[i][j]);
#pragma unroll
            for (int j = 0; j < 4; j++) trow[64 + tc * 4 + j] = gelu_exact(acc[i][4 + j]);
        }
    }

    float acc2[2][8];
#pragma unroll
    for (int i = 0; i < 2; i++)
#pragma unroll
        for (int j = 0; j < 8; j++)
            acc2[i][j] = fb2[(j < 4 ? tc * 4 + j : 64 + tc * 4 + j - 4)];
    for (int kc = 0; kc < 4; kc++) {
        __syncthreads();
        for (int i = tid; i < 4096; i += 256) {
            int k = i >> 5, c4 = i & 31;
            ((float4*)&Wsh[k * 128])[c4] = ((const float4*)&fW2[(size_t)(kc * 128 + k) * 128])[c4];
        }
        __syncthreads();
#pragma unroll 4
        for (int kk = 0; kk < 128; kk++) {
            float4 b0 = *(const float4*)&Wsh[kk * 128 + tc * 4];
            float4 b1v = *(const float4*)&Wsh[kk * 128 + 64 + tc * 4];
#pragma unroll
            for (int i = 0; i < 2; i++) {
                float a = Tsh[(tr * 2 + i) * 516 + kc * 128 + kk];
                acc2[i][0] = fmaf(a, b0.x, acc2[i][0]); acc2[i][1] = fmaf(a, b0.y, acc2[i][1]);
                acc2[i][2] = fmaf(a, b0.z, acc2[i][2]); acc2[i][3] = fmaf(a, b0.w, acc2[i][3]);
                acc2[i][4] = fmaf(a, b1v.x, acc2[i][4]); acc2[i][5] = fmaf(a, b1v.y, acc2[i][5]);
                acc2[i][6] = fmaf(a, b1v.z, acc2[i][6]); acc2[i][7] = fmaf(a, b1v.w, acc2[i][7]);
            }
        }
    }

    __syncthreads();
    float* Vsh = Tsh;
#pragma unroll
    for (int i = 0; i < 2; i++) {
        const int r = tr * 2 + i;
#pragma unroll
        for (int j = 0; j < 4; j++) Vsh[r * 132 + tc * 4 + j]      = H1sh[r * 132 + tc * 4 + j] + acc2[i][j];
#pragma unroll
        for (int j = 0; j < 4; j++) Vsh[r * 132 + 64 + tc * 4 + j] = H1sh[r * 132 + 64 + tc * 4 + j] + acc2[i][4 + j];
    }
    __syncthreads();
    for (int r = wid; r < 32; r += 8) {
        const int c0 = lane * 4;
        float v0 = Vsh[r * 132 + c0], v1 = Vsh[r * 132 + c0 + 1];
        float v2 = Vsh[r * 132 + c0 + 2], v3 = Vsh[r * 132 + c0 + 3];
        float s = v0 + v1 + v2 + v3;
#pragma unroll
        for (int o = 16; o; o >>= 1) s += __shfl_xor_sync(0xffffffffu, s, o);
        float mu = s * (1.f / 128.f);
        float d0 = v0 - mu, d1 = v1 - mu, d2 = v2 - mu, d3 = v3 - mu;
        float q = d0 * d0 + d1 * d1 + d2 * d2 + d3 * d3;
#pragma unroll
        for (int o = 16; o; o >>= 1) q += __shfl_xor_sync(0xffffffffu, q, o);
        float rs = rsqrtf(q * (1.f / 128.f) + 1e-5f);
        float4 o4;
        o4.x = d0 * rs * g2[c0]     + b2[c0];
        o4.y = d1 * rs * g2[c0 + 1] + b2[c0 + 1];
        o4.z = d2 * rs * g2[c0 + 2] + b2[c0 + 2];
        o4.w = d3 * rs * g2[c0 + 3] + b2[c0 + 3];
        *(float4*)&out[(size_t)(m0 + r) * NH + c0] = o4;
    }
}

// ---------------------------------------------------------------------------
extern "C" void kernel_launch(void* const* d_in, const int* in_sizes, int n_in,
                              void* d_out, int out_size) {
    const float* node_h   = (const float*)d_in[0];
    const float* edge_h   = (const float*)d_in[1];
    const int*   edge_idx = (const int*)d_in[2];
    const float* seq_emb  = (const float*)d_in[3];
    const float* ar_mask  = (const float*)d_in[4];
    const float* mW1 = (const float*)d_in[5];
    const float* mb1 = (const float*)d_in[6];
    const float* mW2 = (const float*)d_in[7];
    const float* mb2 = (const float*)d_in[8];
    const float* mW3 = (const float*)d_in[9];
    const float* mb3 = (const float*)d_in[10];
    const float* fW1 = (const float*)d_in[11];
    const float* fb1 = (const float*)d_in[12];
    const float* fW2 = (const float*)d_in[13];
    const float* fb2 = (const float*)d_in[14];
    const float* g1  = (const float*)d_in[15];
    const float* b1  = (const float*)d_in[16];
    const float* g2  = (const float*)d_in[17];
    const float* b2  = (const float*)d_in[18];
    float* out = (float*)d_out;

    int dev = 0;
    cudaGetDevice(&dev);
    int nsm = 148;
    cudaDeviceGetAttribute(&nsm, cudaDevAttrMultiProcessorCount, dev);

    const size_t smem1 = (size_t)(16384 + 64 * 132) * sizeof(float);
    const size_t smem3 = (size_t)(32 * 132 + 32 * 516 + 16384) * sizeof(float);

    cudaFuncSetAttribute(k1_pre, cudaFuncAttributeMaxDynamicSharedMemorySize, (int)smem1);
    cudaFuncSetAttribute(k2_msg, cudaFuncAttributeMaxDynamicSharedMemorySize, (int)S_K2TOT);
    cudaFuncSetAttribute(k3_ff,  cudaFuncAttributeMaxDynamicSharedMemorySize, (int)smem3);

    dim3 grid1(NRES / 64, 3);
    k1_pre<<<grid1, 256, smem1>>>(node_h, seq_emb, mW1);

    const int ngroups = NRES / 8;
    k2_msg<<<nsm, 512, S_K2TOT>>>(edge_h, edge_idx, ar_mask,
                                  mW1, mb1, mW2, mb2, ngroups);

    k3_ff<<<NRES / 32, 256, smem3>>>(node_h, mW3, mb3, fW1, fb1, fW2, fb2,
                                     g1, b1, g2, b2, out);
}